// round 1
// baseline (speedup 1.0000x reference)
#include <cuda_runtime.h>
#include <math.h>

// Problem dims (fixed by the dataset)
#define B_  8
#define S_  2048
#define D_  512
#define NT_ (S_/128)      // 16 column tiles per row in scores

// GEMM tiling
#define BM 128
#define BN 128
#define BK 16
#define TM 8
#define TN 8

// Scratch (no runtime allocation allowed)
__device__ float g_Q[B_*S_*D_];
__device__ float g_K[B_*S_*D_];
__device__ float g_psum[B_*S_*NT_];

// ---------------------------------------------------------------------------
// Kernel 1: C[M,512] = A[M,512] @ W[512,512] + bias   (row-major everywhere)
// ---------------------------------------------------------------------------
__global__ __launch_bounds__(256)
void gemm_bias_kernel(const float* __restrict__ A,
                      const float* __restrict__ W,
                      const float* __restrict__ bias,
                      float* __restrict__ C)
{
    __shared__ float As[BK][BM+4];
    __shared__ float Bs[BK][BN];

    const int tid = threadIdx.x;
    const int tx  = tid & 15;        // 0..15 -> n direction
    const int ty  = tid >> 4;        // 0..15 -> m direction
    const int m0  = blockIdx.y * BM;
    const int n0  = blockIdx.x * BN;

    float acc[TM][TN];
    #pragma unroll
    for (int i = 0; i < TM; i++)
        #pragma unroll
        for (int j = 0; j < TN; j++) acc[i][j] = 0.0f;

    for (int k0 = 0; k0 < D_; k0 += BK) {
        // Load A tile [BM x BK] transposed into As[k][m]
        #pragma unroll
        for (int it = 0; it < 2; it++) {
            int idx = tid + it*256;          // 0..511
            int row = idx >> 2;              // 0..127
            int c4  = (idx & 3) * 4;         // 0,4,8,12
            float4 v = *reinterpret_cast<const float4*>(&A[(size_t)(m0+row)*D_ + k0 + c4]);
            As[c4+0][row] = v.x;
            As[c4+1][row] = v.y;
            As[c4+2][row] = v.z;
            As[c4+3][row] = v.w;
        }
        // Load W tile [BK x BN] directly
        #pragma unroll
        for (int it = 0; it < 2; it++) {
            int idx = tid + it*256;          // 0..511
            int row = idx >> 5;              // 0..15
            int c4  = (idx & 31) * 4;        // 0..124
            *reinterpret_cast<float4*>(&Bs[row][c4]) =
                *reinterpret_cast<const float4*>(&W[(size_t)(k0+row)*D_ + n0 + c4]);
        }
        __syncthreads();

        #pragma unroll
        for (int kk = 0; kk < BK; kk++) {
            float a[TM], b[TN];
            #pragma unroll
            for (int i = 0; i < TM; i++) a[i] = As[kk][ty*TM + i];
            #pragma unroll
            for (int j = 0; j < TN; j++) b[j] = Bs[kk][tx*TN + j];
            #pragma unroll
            for (int i = 0; i < TM; i++)
                #pragma unroll
                for (int j = 0; j < TN; j++)
                    acc[i][j] = fmaf(a[i], b[j], acc[i][j]);
        }
        __syncthreads();
    }

    // Epilogue: + bias, store
    float bv[TN];
    #pragma unroll
    for (int j = 0; j < TN; j++) bv[j] = bias[n0 + tx*TN + j];

    #pragma unroll
    for (int i = 0; i < TM; i++) {
        float out0[4], out1[4];
        #pragma unroll
        for (int j = 0; j < 4; j++) { out0[j] = acc[i][j] + bv[j]; out1[j] = acc[i][4+j] + bv[4+j]; }
        float* cp = &C[(size_t)(m0 + ty*TM + i)*D_ + n0 + tx*TN];
        *reinterpret_cast<float4*>(cp)   = *reinterpret_cast<float4*>(out0);
        *reinterpret_cast<float4*>(cp+4) = *reinterpret_cast<float4*>(out1);
    }
}

// ---------------------------------------------------------------------------
// Kernel 2: per batch b:  E[m,n] = exp( (Q_b[m,:] . K_b[n,:]) / sqrt(D) )
//           written to out; per-(row, n-tile) partial sums -> g_psum
// ---------------------------------------------------------------------------
__global__ __launch_bounds__(256)
void scores_exp_kernel(const float* __restrict__ Q,
                       const float* __restrict__ K,
                       float* __restrict__ out,
                       float* __restrict__ psum)
{
    __shared__ float Qs[BK][BM+4];
    __shared__ float Ks[BK][BN+4];
    __shared__ float sred[BM][17];

    const int tid = threadIdx.x;
    const int tx  = tid & 15;
    const int ty  = tid >> 4;
    const int b   = blockIdx.z;
    const int m0  = blockIdx.y * BM;
    const int n0  = blockIdx.x * BN;

    const float* Qb = Q + (size_t)b * S_ * D_;
    const float* Kb = K + (size_t)b * S_ * D_;

    float acc[TM][TN];
    #pragma unroll
    for (int i = 0; i < TM; i++)
        #pragma unroll
        for (int j = 0; j < TN; j++) acc[i][j] = 0.0f;

    for (int k0 = 0; k0 < D_; k0 += BK) {
        #pragma unroll
        for (int it = 0; it < 2; it++) {
            int idx = tid + it*256;
            int row = idx >> 2;
            int c4  = (idx & 3) * 4;
            float4 v = *reinterpret_cast<const float4*>(&Qb[(size_t)(m0+row)*D_ + k0 + c4]);
            Qs[c4+0][row] = v.x; Qs[c4+1][row] = v.y; Qs[c4+2][row] = v.z; Qs[c4+3][row] = v.w;
            float4 w = *reinterpret_cast<const float4*>(&Kb[(size_t)(n0+row)*D_ + k0 + c4]);
            Ks[c4+0][row] = w.x; Ks[c4+1][row] = w.y; Ks[c4+2][row] = w.z; Ks[c4+3][row] = w.w;
        }
        __syncthreads();

        #pragma unroll
        for (int kk = 0; kk < BK; kk++) {
            float a[TM], bb[TN];
            #pragma unroll
            for (int i = 0; i < TM; i++) a[i]  = Qs[kk][ty*TM + i];
            #pragma unroll
            for (int j = 0; j < TN; j++) bb[j] = Ks[kk][tx*TN + j];
            #pragma unroll
            for (int i = 0; i < TM; i++)
                #pragma unroll
                for (int j = 0; j < TN; j++)
                    acc[i][j] = fmaf(a[i], bb[j], acc[i][j]);
        }
        __syncthreads();
    }

    // Epilogue: exp(score/sqrt(D)), row partial sums, store E
    const float inv_sqrt_d = 0.044194173824159216f;   // 1/sqrt(512)
    float rsum[TM];
    #pragma unroll
    for (int i = 0; i < TM; i++) rsum[i] = 0.0f;

    #pragma unroll
    for (int i = 0; i < TM; i++) {
        float e0[4], e1[4];
        #pragma unroll
        for (int j = 0; j < 4; j++) {
            e0[j] = expf(acc[i][j]   * inv_sqrt_d);
            e1[j] = expf(acc[i][4+j] * inv_sqrt_d);
            rsum[i] += e0[j] + e1[j];
        }
        float* op = &out[((size_t)(b*S_ + m0 + ty*TM + i))*S_ + n0 + tx*TN];
        *reinterpret_cast<float4*>(op)   = *reinterpret_cast<float4*>(e0);
        *reinterpret_cast<float4*>(op+4) = *reinterpret_cast<float4*>(e1);
    }

    // Reduce row sums across the 16 tx lanes (deterministic fixed order)
    #pragma unroll
    for (int i = 0; i < TM; i++) sred[ty*TM + i][tx] = rsum[i];
    __syncthreads();

    if (tid < BM) {
        float s = 0.0f;
        #pragma unroll
        for (int t = 0; t < 16; t++) s += sred[tid][t];
        psum[((size_t)(b*S_ + m0 + tid))*NT_ + blockIdx.x] = s;
    }
}

// ---------------------------------------------------------------------------
// Kernel 3: normalize each row of out by its total sum
// ---------------------------------------------------------------------------
__global__ __launch_bounds__(256)
void normalize_kernel(float* __restrict__ out, const float* __restrict__ psum)
{
    const int row = blockIdx.x;       // 0..B*S-1
    __shared__ float s_inv;
    if (threadIdx.x == 0) {
        float s = 0.0f;
        #pragma unroll
        for (int t = 0; t < NT_; t++) s += psum[(size_t)row*NT_ + t];
        s_inv = 1.0f / s;
    }
    __syncthreads();
    const float iv = s_inv;
    float4* p = reinterpret_cast<float4*>(out + (size_t)row * S_);
    for (int j = threadIdx.x; j < S_/4; j += 256) {
        float4 v = p[j];
        v.x *= iv; v.y *= iv; v.z *= iv; v.w *= iv;
        p[j] = v;
    }
}

// ---------------------------------------------------------------------------
// Launcher
// ---------------------------------------------------------------------------
extern "C" void kernel_launch(void* const* d_in, const int* in_sizes, int n_in,
                              void* d_out, int out_size)
{
    const float* x  = (const float*)d_in[0];
    const float* Wq = (const float*)d_in[1];
    const float* bq = (const float*)d_in[2];
    const float* Wk = (const float*)d_in[3];
    const float* bk = (const float*)d_in[4];
    // d_in[5], d_in[6] (Wv, bv) are unused by the reference output.
    float* out = (float*)d_out;

    float *qptr, *kptr, *pptr;
    cudaGetSymbolAddress((void**)&qptr, g_Q);
    cudaGetSymbolAddress((void**)&kptr, g_K);
    cudaGetSymbolAddress((void**)&pptr, g_psum);

    // 1) Projections: Q = x@Wq + bq, K = x@Wk + bk   (M = B*S = 16384)
    dim3 gblock(256);
    dim3 ggrid(D_/BN, (B_*S_)/BM);            // (4, 128)
    gemm_bias_kernel<<<ggrid, gblock>>>(x, Wq, bq, qptr);
    gemm_bias_kernel<<<ggrid, gblock>>>(x, Wk, bk, kptr);

    // 2) Scores + exp + partial row sums
    dim3 sgrid(S_/BN, S_/BM, B_);             // (16, 16, 8)
    scores_exp_kernel<<<sgrid, gblock>>>(qptr, kptr, out, pptr);

    // 3) Row normalize
    normalize_kernel<<<B_*S_, 256>>>(out, pptr);
}

// round 3
// speedup vs baseline: 2.5523x; 2.5523x over previous
#include <cuda_runtime.h>
#include <cuda_bf16.h>
#include <cstdint>
#include <math.h>

#define B_  8
#define S_  2048
#define D_  512
#define NT_ 16          // psum slots per row (S_/128 column tiles)

// ---- GEMM tile config ----
#define BM 128
#define BN 128
#define KC 64           // K elements per chunk (128B of bf16 per row)
#define NCHUNK (D_/KC)  // 8

// stage layout (bytes): four 128x64 bf16 tiles
#define STG_A_HI 0
#define STG_A_LO 16384
#define STG_B_HI 32768
#define STG_B_LO 49152
#define STAGE_BYTES 65536
#define SMEM_DYN (1024 + 2*STAGE_BYTES)

// (1/sqrt(512)) * log2(e)
#define EXP2_SCALE 0.06376070918938434f

// ---------------- scratch (device globals; no runtime alloc) ----------------
__device__ __nv_bfloat16 g_xhi[B_*S_*D_];
__device__ __nv_bfloat16 g_xlo[B_*S_*D_];
__device__ __nv_bfloat16 g_wqt_hi[D_*D_];
__device__ __nv_bfloat16 g_wqt_lo[D_*D_];
__device__ __nv_bfloat16 g_wkt_hi[D_*D_];
__device__ __nv_bfloat16 g_wkt_lo[D_*D_];
__device__ __nv_bfloat16 g_qhi[B_*S_*D_];
__device__ __nv_bfloat16 g_qlo[B_*S_*D_];
__device__ __nv_bfloat16 g_khi[B_*S_*D_];
__device__ __nv_bfloat16 g_klo[B_*S_*D_];
__device__ float         g_psum[B_*S_*NT_];

// ---------------- helpers ----------------
__device__ __forceinline__ uint32_t smem_u32(const void* p) {
    uint32_t a;
    asm("{ .reg .u64 t; cvta.to.shared.u64 t, %1; cvt.u32.u64 %0, t; }" : "=r"(a) : "l"(p));
    return a;
}
__device__ __forceinline__ uint32_t swz128(uint32_t off) {
    return off ^ ((off >> 3) & 0x70);
}
__device__ __forceinline__ void cp_async16(uint32_t dst, const void* src) {
    asm volatile("cp.async.cg.shared.global [%0], [%1], 16;" :: "r"(dst), "l"(src));
}
__device__ __forceinline__ void cp_commit() {
    asm volatile("cp.async.commit_group;" ::: "memory");
}
__device__ __forceinline__ void ldsm_x4(uint32_t& r0, uint32_t& r1, uint32_t& r2, uint32_t& r3,
                                        uint32_t addr) {
    asm volatile("ldmatrix.sync.aligned.m8n8.x4.shared.b16 {%0,%1,%2,%3}, [%4];"
                 : "=r"(r0), "=r"(r1), "=r"(r2), "=r"(r3) : "r"(addr));
}
__device__ __forceinline__ void mma16816(float* c, const uint32_t* a, const uint32_t* b) {
    asm volatile(
        "mma.sync.aligned.m16n8k16.row.col.f32.bf16.bf16.f32 "
        "{%0,%1,%2,%3}, {%4,%5,%6,%7}, {%8,%9}, {%0,%1,%2,%3};"
        : "+f"(c[0]), "+f"(c[1]), "+f"(c[2]), "+f"(c[3])
        : "r"(a[0]), "r"(a[1]), "r"(a[2]), "r"(a[3]), "r"(b[0]), "r"(b[1]));
}

// ---------------- prep kernels ----------------
__global__ __launch_bounds__(256)
void split_x_kernel(const float* __restrict__ in,
                    __nv_bfloat16* __restrict__ hi, __nv_bfloat16* __restrict__ lo)
{
    int i = blockIdx.x * 256 + threadIdx.x;       // per float4
    float4 v = reinterpret_cast<const float4*>(in)[i];
    float f[4] = {v.x, v.y, v.z, v.w};
    __nv_bfloat16 h[4], l[4];
    #pragma unroll
    for (int j = 0; j < 4; j++) {
        h[j] = __float2bfloat16(f[j]);
        l[j] = __float2bfloat16(f[j] - __bfloat162float(h[j]));
    }
    *reinterpret_cast<uint2*>(hi + (size_t)i*4) = *reinterpret_cast<uint2*>(h);
    *reinterpret_cast<uint2*>(lo + (size_t)i*4) = *reinterpret_cast<uint2*>(l);
}

__global__ __launch_bounds__(1024)
void transpose_split_kernel(const float* __restrict__ W,
                            __nv_bfloat16* __restrict__ thi, __nv_bfloat16* __restrict__ tlo)
{
    __shared__ float t[32][33];
    int n0 = blockIdx.x * 32, k0 = blockIdx.y * 32;
    t[threadIdx.y][threadIdx.x] = W[(size_t)(k0 + threadIdx.y)*D_ + n0 + threadIdx.x];
    __syncthreads();
    float v = t[threadIdx.x][threadIdx.y];        // = W[k0+tx][n0+ty]
    __nv_bfloat16 h = __float2bfloat16(v);
    __nv_bfloat16 l = __float2bfloat16(v - __bfloat162float(h));
    size_t o = (size_t)(n0 + threadIdx.y)*D_ + k0 + threadIdx.x;
    thi[o] = h;
    tlo[o] = l;
}

// ---------------- chunk loader ----------------
__device__ __forceinline__ void load_chunk(uint32_t stage,
    const __nv_bfloat16* __restrict__ aHi, const __nv_bfloat16* __restrict__ aLo,
    const __nv_bfloat16* __restrict__ bHi, const __nv_bfloat16* __restrict__ bLo,
    int kof, int tid)
{
    #pragma unroll
    for (int t = 0; t < 2; t++) {
        int seg = t*512 + tid;                 // 0..1023 -> 128 rows x 8 segs
        int row = seg >> 3, j = seg & 7;
        uint32_t so = swz128((uint32_t)(row*128 + j*16));
        const size_t go = (size_t)row * D_ + kof + j*8;
        cp_async16(stage + STG_A_HI + so, aHi + go);
        cp_async16(stage + STG_A_LO + so, aLo + go);
        cp_async16(stage + STG_B_HI + so, bHi + go);
        cp_async16(stage + STG_B_LO + so, bLo + go);
    }
}

// ---------------- NT GEMM: C = A @ B^T  (bf16 hi/lo 3-term split) ----------------
// MODE 0: projection -> out = A@B^T + bias, stored bf16 hi/lo
// MODE 1: scores     -> out = exp2(scale * A@B^T) fp32 + per-tile row sums
template<int MODE>
__global__ __launch_bounds__(512, 1)
void gemm_nt_kernel(const __nv_bfloat16* __restrict__ aHiBase,
                    const __nv_bfloat16* __restrict__ aLoBase,
                    const __nv_bfloat16* __restrict__ bHiBase,
                    const __nv_bfloat16* __restrict__ bLoBase,
                    const float* __restrict__ bias,
                    __nv_bfloat16* __restrict__ outHi,
                    __nv_bfloat16* __restrict__ outLo,
                    float* __restrict__ outF,
                    float* __restrict__ psum)
{
    extern __shared__ char smem_raw[];
    const uint32_t sb = (smem_u32(smem_raw) + 1023u) & ~1023u;
    __shared__ float s_rowsum[128][4];

    const int tid    = threadIdx.x;
    const int lane   = tid & 31;
    const int wid    = tid >> 5;
    const int warp_m = wid & 3;      // 4 warps in M (32 rows each)
    const int warp_n = wid >> 2;     // 4 warps in N (32 cols each)

    int arow0, brow0, ncol0;
    if (MODE == 0) {
        arow0 = blockIdx.y * BM;
        brow0 = blockIdx.x * BN;
        ncol0 = brow0;
    } else {
        const int b = blockIdx.z;
        arow0 = b * S_ + blockIdx.y * BM;
        brow0 = b * S_ + blockIdx.x * BN;
        ncol0 = blockIdx.x * BN;
    }
    const __nv_bfloat16* aHi = aHiBase + (size_t)arow0 * D_;
    const __nv_bfloat16* aLo = aLoBase + (size_t)arow0 * D_;
    const __nv_bfloat16* bHi = bHiBase + (size_t)brow0 * D_;
    const __nv_bfloat16* bLo = bLoBase + (size_t)brow0 * D_;

    // ldmatrix lane geometry
    const int laneR  = lane & 15;
    const int laneCB = (lane >> 4) * 16;              // byte offset: second 8-col group
    const uint32_t aRowB = (uint32_t)(warp_m*32 + laneR) * 128;
    const uint32_t bRowB = (uint32_t)(warp_n*32 + laneR) * 128;

    float acc[2][4][4];
    #pragma unroll
    for (int i = 0; i < 2; i++)
        #pragma unroll
        for (int j = 0; j < 4; j++)
            #pragma unroll
            for (int k = 0; k < 4; k++) acc[i][j][k] = 0.0f;

    // prologue: stage 0
    load_chunk(sb + 1024, aHi, aLo, bHi, bLo, 0, tid);
    cp_commit();

    for (int c = 0; c < NCHUNK; c++) {
        if (c + 1 < NCHUNK) {
            load_chunk(sb + 1024 + ((c+1)&1)*STAGE_BYTES, aHi, aLo, bHi, bLo, (c+1)*KC, tid);
            cp_commit();
            asm volatile("cp.async.wait_group 1;" ::: "memory");
        } else {
            asm volatile("cp.async.wait_group 0;" ::: "memory");
        }
        __syncthreads();

        const uint32_t stage = sb + 1024 + (c&1)*STAGE_BYTES;
        #pragma unroll
        for (int kk = 0; kk < 4; kk++) {
            const uint32_t kb = (uint32_t)(kk*32 + laneCB);

            uint32_t ahi[2][4], alo[2][4];
            #pragma unroll
            for (int f = 0; f < 2; f++) {
                uint32_t off = swz128(aRowB + (uint32_t)f*(16*128) + kb);
                ldsm_x4(ahi[f][0], ahi[f][1], ahi[f][2], ahi[f][3], stage + STG_A_HI + off);
                ldsm_x4(alo[f][0], alo[f][1], alo[f][2], alo[f][3], stage + STG_A_LO + off);
            }
            uint32_t bhi[4][2], blo[4][2];
            #pragma unroll
            for (int g = 0; g < 2; g++) {
                uint32_t off = swz128(bRowB + (uint32_t)g*(16*128) + kb);
                uint32_t t0, t1, t2, t3;
                ldsm_x4(t0, t1, t2, t3, stage + STG_B_HI + off);
                bhi[2*g][0] = t0; bhi[2*g][1] = t2; bhi[2*g+1][0] = t1; bhi[2*g+1][1] = t3;
                ldsm_x4(t0, t1, t2, t3, stage + STG_B_LO + off);
                blo[2*g][0] = t0; blo[2*g][1] = t2; blo[2*g+1][0] = t1; blo[2*g+1][1] = t3;
            }
            #pragma unroll
            for (int mf = 0; mf < 2; mf++)
                #pragma unroll
                for (int nf = 0; nf < 4; nf++) {
                    mma16816(acc[mf][nf], ahi[mf], bhi[nf]);
                    mma16816(acc[mf][nf], ahi[mf], blo[nf]);
                    mma16816(acc[mf][nf], alo[mf], bhi[nf]);
                }
        }
        __syncthreads();
    }

    // ---- epilogue ----
    const int g = lane >> 2, q = lane & 3;

    if (MODE == 1) {
        float rs[4] = {0.f, 0.f, 0.f, 0.f};
        #pragma unroll
        for (int mf = 0; mf < 2; mf++) {
            const size_t row0 = (size_t)arow0 + warp_m*32 + mf*16 + g;
            #pragma unroll
            for (int nf = 0; nf < 4; nf++) {
                const int col = ncol0 + warp_n*32 + nf*8 + q*2;
                float e0 = exp2f(acc[mf][nf][0] * EXP2_SCALE);
                float e1 = exp2f(acc[mf][nf][1] * EXP2_SCALE);
                float e2 = exp2f(acc[mf][nf][2] * EXP2_SCALE);
                float e3 = exp2f(acc[mf][nf][3] * EXP2_SCALE);
                *reinterpret_cast<float2*>(&outF[row0*S_ + col])     = make_float2(e0, e1);
                *reinterpret_cast<float2*>(&outF[(row0+8)*S_ + col]) = make_float2(e2, e3);
                rs[mf*2 + 0] += e0 + e1;
                rs[mf*2 + 1] += e2 + e3;
            }
        }
        #pragma unroll
        for (int i = 0; i < 4; i++) {
            rs[i] += __shfl_xor_sync(0xffffffffu, rs[i], 1);
            rs[i] += __shfl_xor_sync(0xffffffffu, rs[i], 2);
        }
        if (q == 0) {
            #pragma unroll
            for (int i = 0; i < 4; i++)
                s_rowsum[warp_m*32 + (i>>1)*16 + (i&1)*8 + g][warp_n] = rs[i];
        }
        __syncthreads();
        if (tid < 128) {
            float s = s_rowsum[tid][0] + s_rowsum[tid][1] + s_rowsum[tid][2] + s_rowsum[tid][3];
            psum[((size_t)arow0 + tid)*NT_ + blockIdx.x] = s;
        }
    } else {
        #pragma unroll
        for (int mf = 0; mf < 2; mf++) {
            const size_t row0 = (size_t)arow0 + warp_m*32 + mf*16 + g;
            #pragma unroll
            for (int nf = 0; nf < 4; nf++) {
                const int col = ncol0 + warp_n*32 + nf*8 + q*2;
                const float b0 = __ldg(&bias[col]);
                const float b1 = __ldg(&bias[col+1]);
                float v0 = acc[mf][nf][0] + b0;
                float v1 = acc[mf][nf][1] + b1;
                float v2 = acc[mf][nf][2] + b0;
                float v3 = acc[mf][nf][3] + b1;
                __nv_bfloat162 h01, l01, h23, l23;
                h01.x = __float2bfloat16(v0); h01.y = __float2bfloat16(v1);
                l01.x = __float2bfloat16(v0 - __bfloat162float(h01.x));
                l01.y = __float2bfloat16(v1 - __bfloat162float(h01.y));
                h23.x = __float2bfloat16(v2); h23.y = __float2bfloat16(v3);
                l23.x = __float2bfloat16(v2 - __bfloat162float(h23.x));
                l23.y = __float2bfloat16(v3 - __bfloat162float(h23.y));
                *reinterpret_cast<__nv_bfloat162*>(&outHi[row0*D_ + col])     = h01;
                *reinterpret_cast<__nv_bfloat162*>(&outLo[row0*D_ + col])     = l01;
                *reinterpret_cast<__nv_bfloat162*>(&outHi[(row0+8)*D_ + col]) = h23;
                *reinterpret_cast<__nv_bfloat162*>(&outLo[(row0+8)*D_ + col]) = l23;
            }
        }
    }
}

// ---------------- normalize ----------------
__global__ __launch_bounds__(256)
void normalize_kernel(float* __restrict__ out, const float* __restrict__ psum)
{
    const int row = blockIdx.x;
    __shared__ float s_inv;
    if (threadIdx.x == 0) {
        float s = 0.0f;
        #pragma unroll
        for (int t = 0; t < NT_; t++) s += psum[(size_t)row*NT_ + t];
        s_inv = 1.0f / s;
    }
    __syncthreads();
    const float iv = s_inv;
    float4* p = reinterpret_cast<float4*>(out + (size_t)row * S_);
    #pragma unroll
    for (int j = threadIdx.x; j < S_/4; j += 256) {
        float4 v = p[j];
        v.x *= iv; v.y *= iv; v.z *= iv; v.w *= iv;
        p[j] = v;
    }
}

// ---------------- launcher ----------------
extern "C" void kernel_launch(void* const* d_in, const int* in_sizes, int n_in,
                              void* d_out, int out_size)
{
    const float* x  = (const float*)d_in[0];
    const float* Wq = (const float*)d_in[1];
    const float* bq = (const float*)d_in[2];
    const float* Wk = (const float*)d_in[3];
    const float* bk = (const float*)d_in[4];
    float* out = (float*)d_out;

    __nv_bfloat16 *xhi, *xlo, *wqh, *wql, *wkh, *wkl, *qhi, *qlo, *khi, *klo;
    float *pptr;
    cudaGetSymbolAddress((void**)&xhi, g_xhi);
    cudaGetSymbolAddress((void**)&xlo, g_xlo);
    cudaGetSymbolAddress((void**)&wqh, g_wqt_hi);
    cudaGetSymbolAddress((void**)&wql, g_wqt_lo);
    cudaGetSymbolAddress((void**)&wkh, g_wkt_hi);
    cudaGetSymbolAddress((void**)&wkl, g_wkt_lo);
    cudaGetSymbolAddress((void**)&qhi, g_qhi);
    cudaGetSymbolAddress((void**)&qlo, g_qlo);
    cudaGetSymbolAddress((void**)&khi, g_khi);
    cudaGetSymbolAddress((void**)&klo, g_klo);
    cudaGetSymbolAddress((void**)&pptr, g_psum);

    cudaFuncSetAttribute(gemm_nt_kernel<0>, cudaFuncAttributeMaxDynamicSharedMemorySize, SMEM_DYN);
    cudaFuncSetAttribute(gemm_nt_kernel<1>, cudaFuncAttributeMaxDynamicSharedMemorySize, SMEM_DYN);

    // 1) splits / transposes
    split_x_kernel<<<(B_*S_*D_/4 + 255)/256, 256>>>(x, xhi, xlo);
    dim3 tb(32, 32);
    dim3 tg(D_/32, D_/32);
    transpose_split_kernel<<<tg, tb>>>(Wq, wqh, wql);
    transpose_split_kernel<<<tg, tb>>>(Wk, wkh, wkl);

    // 2) projections: Q = x@Wq + bq, K = x@Wk + bk (stored as bf16 hi/lo)
    dim3 pg(D_/BN, (B_*S_)/BM);          // (4, 128)
    gemm_nt_kernel<0><<<pg, 512, SMEM_DYN>>>(xhi, xlo, wqh, wql, bq, qhi, qlo, nullptr, nullptr);
    gemm_nt_kernel<0><<<pg, 512, SMEM_DYN>>>(xhi, xlo, wkh, wkl, bk, khi, klo, nullptr, nullptr);

    // 3) scores: E = exp(Q K^T / sqrt(d)) + row partial sums
    dim3 sg(S_/BN, S_/BM, B_);           // (16, 16, 8)
    gemm_nt_kernel<1><<<sg, 512, SMEM_DYN>>>(qhi, qlo, khi, klo, nullptr, nullptr, nullptr, out, pptr);

    // 4) normalize
    normalize_kernel<<<B_*S_, 256>>>(out, pptr);
}

// round 4
// speedup vs baseline: 3.0571x; 1.1978x over previous
#include <cuda_runtime.h>
#include <cuda_bf16.h>
#include <cstdint>
#include <math.h>

#define B_  8
#define S_  2048
#define D_  512
#define NT_ 16          // psum slots per row (S_/128 column tiles)

// ---- GEMM tile config ----
#define BM 128
#define BN 128
#define KC 64           // K elements per chunk (128B of bf16 per row)
#define NCHUNK (D_/KC)  // 8
#define NSTAGE 3

// stage layout (bytes): four 128x64 bf16 tiles
#define STG_A_HI 0
#define STG_A_LO 16384
#define STG_B_HI 32768
#define STG_B_LO 49152
#define STAGE_BYTES 65536
#define SMEM_DYN (1024 + NSTAGE*STAGE_BYTES)

// (1/sqrt(512)) * log2(e)
#define EXP2_SCALE 0.06376070918938434f

// ---------------- scratch (device globals; no runtime alloc) ----------------
__device__ __nv_bfloat16 g_xhi[B_*S_*D_];
__device__ __nv_bfloat16 g_xlo[B_*S_*D_];
__device__ __nv_bfloat16 g_m2hi[D_*D_];     // B-layout: m2t[g*512+f] = (WqWk^T)[f,g]
__device__ __nv_bfloat16 g_m2lo[D_*D_];
__device__ __nv_bfloat16 g_uhi[B_*S_*D_];   // u = x @ M2
__device__ __nv_bfloat16 g_ulo[B_*S_*D_];
__device__ float         g_v2[D_];          // Wk @ bq
__device__ float         g_rk[B_*S_];       // (x[n].v2) * EXP2_SCALE
__device__ float         g_psum[B_*S_*NT_];
__device__ float         g_inv[B_*S_];

// ---------------- helpers ----------------
__device__ __forceinline__ uint32_t smem_u32(const void* p) {
    uint32_t a;
    asm("{ .reg .u64 t; cvta.to.shared.u64 t, %1; cvt.u32.u64 %0, t; }" : "=r"(a) : "l"(p));
    return a;
}
__device__ __forceinline__ uint32_t swz128(uint32_t off) {
    return off ^ ((off >> 3) & 0x70);
}
__device__ __forceinline__ void cp_async16(uint32_t dst, const void* src) {
    asm volatile("cp.async.cg.shared.global [%0], [%1], 16;" :: "r"(dst), "l"(src));
}
__device__ __forceinline__ void cp_commit() {
    asm volatile("cp.async.commit_group;" ::: "memory");
}
__device__ __forceinline__ void ldsm_x4(uint32_t& r0, uint32_t& r1, uint32_t& r2, uint32_t& r3,
                                        uint32_t addr) {
    asm volatile("ldmatrix.sync.aligned.m8n8.x4.shared.b16 {%0,%1,%2,%3}, [%4];"
                 : "=r"(r0), "=r"(r1), "=r"(r2), "=r"(r3) : "r"(addr));
}
__device__ __forceinline__ void mma16816(float* c, const uint32_t* a, const uint32_t* b) {
    asm volatile(
        "mma.sync.aligned.m16n8k16.row.col.f32.bf16.bf16.f32 "
        "{%0,%1,%2,%3}, {%4,%5,%6,%7}, {%8,%9}, {%0,%1,%2,%3};"
        : "+f"(c[0]), "+f"(c[1]), "+f"(c[2]), "+f"(c[3])
        : "r"(a[0]), "r"(a[1]), "r"(a[2]), "r"(a[3]), "r"(b[0]), "r"(b[1]));
}

// ---------------- prep kernels ----------------
// v2[g] = sum_d Wk[g,d] * bq[d]      (warp per row)
__global__ __launch_bounds__(256)
void v2_kernel(const float* __restrict__ Wk, const float* __restrict__ bq,
               float* __restrict__ v2)
{
    const int lane = threadIdx.x & 31;
    const int wrow = blockIdx.x * 8 + (threadIdx.x >> 5);
    float s = 0.0f;
    #pragma unroll
    for (int i = 0; i < 16; i++) {
        int d = i*32 + lane;
        s += Wk[(size_t)wrow*D_ + d] * bq[d];
    }
    #pragma unroll
    for (int o = 16; o > 0; o >>= 1) s += __shfl_xor_sync(0xffffffffu, s, o);
    if (lane == 0) v2[wrow] = s;
}

// split x into bf16 hi/lo AND compute rk[n] = (x[n].v2)*EXP2_SCALE
__global__ __launch_bounds__(256)
void split_x_rk_kernel(const float* __restrict__ in, const float* __restrict__ v2,
                       __nv_bfloat16* __restrict__ hi, __nv_bfloat16* __restrict__ lo,
                       float* __restrict__ rk)
{
    __shared__ float red[2][4];
    const int tid = threadIdx.x;
    const int rr  = tid >> 7;            // 0..1  (row within block)
    const int t   = tid & 127;           // float4 slot within row
    const size_t row = (size_t)blockIdx.x * 2 + rr;
    const size_t i   = row * 128 + t;    // float4 index

    float4 v = reinterpret_cast<const float4*>(in)[i];
    float f[4] = {v.x, v.y, v.z, v.w};
    __nv_bfloat16 h[4], l[4];
    #pragma unroll
    for (int j = 0; j < 4; j++) {
        h[j] = __float2bfloat16(f[j]);
        l[j] = __float2bfloat16(f[j] - __bfloat162float(h[j]));
    }
    *reinterpret_cast<uint2*>(hi + i*4) = *reinterpret_cast<uint2*>(h);
    *reinterpret_cast<uint2*>(lo + i*4) = *reinterpret_cast<uint2*>(l);

    float4 w = reinterpret_cast<const float4*>(v2)[t];
    float local = v.x*w.x + v.y*w.y + v.z*w.z + v.w*w.w;
    #pragma unroll
    for (int o = 16; o > 0; o >>= 1) local += __shfl_xor_sync(0xffffffffu, local, o);
    if ((tid & 31) == 0) red[rr][(t >> 5)] = local;
    __syncthreads();
    if (t == 0)
        rk[row] = (red[rr][0] + red[rr][1] + red[rr][2] + red[rr][3]) * EXP2_SCALE;
}

// m2t[g,f] = sum_d Wk[g,d]*Wq[f,d], split to bf16 hi/lo at [g*512+f]
__global__ __launch_bounds__(256)
void m2t_kernel(const float* __restrict__ Wk, const float* __restrict__ Wq,
                __nv_bfloat16* __restrict__ m2hi, __nv_bfloat16* __restrict__ m2lo)
{
    __shared__ float sk[32][33];
    __shared__ float sq[32][33];
    const int tid = threadIdx.x;
    const int g0 = blockIdx.y * 32, f0 = blockIdx.x * 32;
    const int ty = tid >> 4, tx = tid & 15;

    float acc[2][2] = {{0.f,0.f},{0.f,0.f}};
    for (int d0 = 0; d0 < D_; d0 += 32) {
        #pragma unroll
        for (int p = 0; p < 4; p++) {
            int e = p*256 + tid;           // 0..1023
            int r = e >> 5, c = e & 31;
            sk[r][c] = Wk[(size_t)(g0+r)*D_ + d0 + c];
            sq[r][c] = Wq[(size_t)(f0+r)*D_ + d0 + c];
        }
        __syncthreads();
        #pragma unroll
        for (int d = 0; d < 32; d++) {
            float k0v = sk[2*ty][d],   k1v = sk[2*ty+1][d];
            float q0v = sq[2*tx][d],   q1v = sq[2*tx+1][d];
            acc[0][0] = fmaf(k0v, q0v, acc[0][0]);
            acc[0][1] = fmaf(k0v, q1v, acc[0][1]);
            acc[1][0] = fmaf(k1v, q0v, acc[1][0]);
            acc[1][1] = fmaf(k1v, q1v, acc[1][1]);
        }
        __syncthreads();
    }
    #pragma unroll
    for (int i = 0; i < 2; i++)
        #pragma unroll
        for (int j = 0; j < 2; j++) {
            float v = acc[i][j];
            __nv_bfloat16 h = __float2bfloat16(v);
            __nv_bfloat16 l = __float2bfloat16(v - __bfloat162float(h));
            size_t o = (size_t)(g0 + 2*ty + i)*D_ + f0 + 2*tx + j;
            m2hi[o] = h;
            m2lo[o] = l;
        }
}

// ---------------- chunk loader ----------------
__device__ __forceinline__ void load_chunk(uint32_t stage,
    const __nv_bfloat16* __restrict__ aHi, const __nv_bfloat16* __restrict__ aLo,
    const __nv_bfloat16* __restrict__ bHi, const __nv_bfloat16* __restrict__ bLo,
    int kof, int tid)
{
    #pragma unroll
    for (int t = 0; t < 2; t++) {
        int seg = t*512 + tid;                 // 0..1023 -> 128 rows x 8 segs
        int row = seg >> 3, j = seg & 7;
        uint32_t so = swz128((uint32_t)(row*128 + j*16));
        const size_t go = (size_t)row * D_ + kof + j*8;
        cp_async16(stage + STG_A_HI + so, aHi + go);
        cp_async16(stage + STG_A_LO + so, aLo + go);
        cp_async16(stage + STG_B_HI + so, bHi + go);
        cp_async16(stage + STG_B_LO + so, bLo + go);
    }
}

// ---------------- NT GEMM: C = A @ B^T  (bf16 hi/lo 3-term split) ----------------
// MODE 0: u-projection -> out = A@B^T, stored bf16 hi/lo
// MODE 1: scores       -> out = exp2(scale*(A@B^T) + rk[n]) fp32 + per-tile row sums
template<int MODE>
__global__ __launch_bounds__(512, 1)
void gemm_nt_kernel(const __nv_bfloat16* __restrict__ aHiBase,
                    const __nv_bfloat16* __restrict__ aLoBase,
                    const __nv_bfloat16* __restrict__ bHiBase,
                    const __nv_bfloat16* __restrict__ bLoBase,
                    const float* __restrict__ rk_s,
                    __nv_bfloat16* __restrict__ outHi,
                    __nv_bfloat16* __restrict__ outLo,
                    float* __restrict__ outF,
                    float* __restrict__ psum)
{
    extern __shared__ char smem_raw[];
    const uint32_t sb = (smem_u32(smem_raw) + 1023u) & ~1023u;
    __shared__ float s_rowsum[128][4];

    const int tid    = threadIdx.x;
    const int lane   = tid & 31;
    const int wid    = tid >> 5;
    const int warp_m = wid & 3;
    const int warp_n = wid >> 2;

    int arow0, brow0, ncol0;
    if (MODE == 0) {
        arow0 = blockIdx.y * BM;
        brow0 = blockIdx.x * BN;
        ncol0 = brow0;
    } else {
        const int b = blockIdx.z;
        arow0 = b * S_ + blockIdx.y * BM;
        brow0 = b * S_ + blockIdx.x * BN;
        ncol0 = blockIdx.x * BN;
    }
    const __nv_bfloat16* aHi = aHiBase + (size_t)arow0 * D_;
    const __nv_bfloat16* aLo = aLoBase + (size_t)arow0 * D_;
    const __nv_bfloat16* bHi = bHiBase + (size_t)brow0 * D_;
    const __nv_bfloat16* bLo = bLoBase + (size_t)brow0 * D_;
    const float* rkb = (MODE == 1) ? (rk_s + (size_t)blockIdx.z * S_) : rk_s;

    const int laneR  = lane & 15;
    const int laneCB = (lane >> 4) * 16;
    const uint32_t aRowB = (uint32_t)(warp_m*32 + laneR) * 128;
    const uint32_t bRowB = (uint32_t)(warp_n*32 + laneR) * 128;

    float acc[2][4][4];
    #pragma unroll
    for (int i = 0; i < 2; i++)
        #pragma unroll
        for (int j = 0; j < 4; j++)
            #pragma unroll
            for (int k = 0; k < 4; k++) acc[i][j][k] = 0.0f;

    load_chunk(sb + 1024, aHi, aLo, bHi, bLo, 0, tid);
    cp_commit();

    for (int c = 0; c < NCHUNK; c++) {
        if (c + 1 < NCHUNK) {
            load_chunk(sb + 1024 + ((c+1)%NSTAGE)*STAGE_BYTES, aHi, aLo, bHi, bLo, (c+1)*KC, tid);
            cp_commit();
            asm volatile("cp.async.wait_group 1;" ::: "memory");
        } else {
            asm volatile("cp.async.wait_group 0;" ::: "memory");
        }
        __syncthreads();

        const uint32_t stage = sb + 1024 + (c%NSTAGE)*STAGE_BYTES;
        #pragma unroll
        for (int kk = 0; kk < 4; kk++) {
            const uint32_t kb = (uint32_t)(kk*32 + laneCB);

            uint32_t ahi[2][4], alo[2][4];
            #pragma unroll
            for (int f = 0; f < 2; f++) {
                uint32_t off = swz128(aRowB + (uint32_t)f*(16*128) + kb);
                ldsm_x4(ahi[f][0], ahi[f][1], ahi[f][2], ahi[f][3], stage + STG_A_HI + off);
                ldsm_x4(alo[f][0], alo[f][1], alo[f][2], alo[f][3], stage + STG_A_LO + off);
            }
            uint32_t bhi[4][2], blo[4][2];
            #pragma unroll
            for (int g = 0; g < 2; g++) {
                uint32_t off = swz128(bRowB + (uint32_t)g*(16*128) + kb);
                uint32_t t0, t1, t2, t3;
                ldsm_x4(t0, t1, t2, t3, stage + STG_B_HI + off);
                bhi[2*g][0] = t0; bhi[2*g][1] = t2; bhi[2*g+1][0] = t1; bhi[2*g+1][1] = t3;
                ldsm_x4(t0, t1, t2, t3, stage + STG_B_LO + off);
                blo[2*g][0] = t0; blo[2*g][1] = t2; blo[2*g+1][0] = t1; blo[2*g+1][1] = t3;
            }
            #pragma unroll
            for (int mf = 0; mf < 2; mf++)
                #pragma unroll
                for (int nf = 0; nf < 4; nf++) {
                    mma16816(acc[mf][nf], ahi[mf], bhi[nf]);
                    mma16816(acc[mf][nf], ahi[mf], blo[nf]);
                    mma16816(acc[mf][nf], alo[mf], bhi[nf]);
                }
        }
        // no trailing barrier: 3-stage ring keeps the write target 2 buffers ahead
    }

    // ---- epilogue ----
    const int g = lane >> 2, q = lane & 3;

    if (MODE == 1) {
        float rs[4] = {0.f, 0.f, 0.f, 0.f};
        #pragma unroll
        for (int mf = 0; mf < 2; mf++) {
            const size_t row0 = (size_t)arow0 + warp_m*32 + mf*16 + g;
            #pragma unroll
            for (int nf = 0; nf < 4; nf++) {
                const int col = ncol0 + warp_n*32 + nf*8 + q*2;
                const float r0 = __ldg(&rkb[col]);
                const float r1 = __ldg(&rkb[col+1]);
                float e0 = exp2f(fmaf(acc[mf][nf][0], EXP2_SCALE, r0));
                float e1 = exp2f(fmaf(acc[mf][nf][1], EXP2_SCALE, r1));
                float e2 = exp2f(fmaf(acc[mf][nf][2], EXP2_SCALE, r0));
                float e3 = exp2f(fmaf(acc[mf][nf][3], EXP2_SCALE, r1));
                *reinterpret_cast<float2*>(&outF[row0*S_ + col])     = make_float2(e0, e1);
                *reinterpret_cast<float2*>(&outF[(row0+8)*S_ + col]) = make_float2(e2, e3);
                rs[mf*2 + 0] += e0 + e1;
                rs[mf*2 + 1] += e2 + e3;
            }
        }
        #pragma unroll
        for (int i = 0; i < 4; i++) {
            rs[i] += __shfl_xor_sync(0xffffffffu, rs[i], 1);
            rs[i] += __shfl_xor_sync(0xffffffffu, rs[i], 2);
        }
        if (q == 0) {
            #pragma unroll
            for (int i = 0; i < 4; i++)
                s_rowsum[warp_m*32 + (i>>1)*16 + (i&1)*8 + g][warp_n] = rs[i];
        }
        __syncthreads();
        if (tid < 128) {
            float s = s_rowsum[tid][0] + s_rowsum[tid][1] + s_rowsum[tid][2] + s_rowsum[tid][3];
            psum[((size_t)arow0 + tid)*NT_ + blockIdx.x] = s;
        }
    } else {
        #pragma unroll
        for (int mf = 0; mf < 2; mf++) {
            const size_t row0 = (size_t)arow0 + warp_m*32 + mf*16 + g;
            #pragma unroll
            for (int nf = 0; nf < 4; nf++) {
                const int col = ncol0 + warp_n*32 + nf*8 + q*2;
                float v0 = acc[mf][nf][0];
                float v1 = acc[mf][nf][1];
                float v2 = acc[mf][nf][2];
                float v3 = acc[mf][nf][3];
                __nv_bfloat162 h01, l01, h23, l23;
                h01.x = __float2bfloat16(v0); h01.y = __float2bfloat16(v1);
                l01.x = __float2bfloat16(v0 - __bfloat162float(h01.x));
                l01.y = __float2bfloat16(v1 - __bfloat162float(h01.y));
                h23.x = __float2bfloat16(v2); h23.y = __float2bfloat16(v3);
                l23.x = __float2bfloat16(v2 - __bfloat162float(h23.x));
                l23.y = __float2bfloat16(v3 - __bfloat162float(h23.y));
                *reinterpret_cast<__nv_bfloat162*>(&outHi[row0*D_ + col])     = h01;
                *reinterpret_cast<__nv_bfloat162*>(&outLo[row0*D_ + col])     = l01;
                *reinterpret_cast<__nv_bfloat162*>(&outHi[(row0+8)*D_ + col]) = h23;
                *reinterpret_cast<__nv_bfloat162*>(&outLo[(row0+8)*D_ + col]) = l23;
            }
        }
    }
}

// ---------------- row-sum inverse + normalize ----------------
__global__ __launch_bounds__(256)
void invsum_kernel(const float* __restrict__ psum, float* __restrict__ inv)
{
    const int row = blockIdx.x * 256 + threadIdx.x;
    const float4* p = reinterpret_cast<const float4*>(psum + (size_t)row * NT_);
    float4 a = p[0], b = p[1], c = p[2], d = p[3];
    float s = ((a.x+a.y)+(a.z+a.w)) + ((b.x+b.y)+(b.z+b.w))
            + ((c.x+c.y)+(c.z+c.w)) + ((d.x+d.y)+(d.z+d.w));
    inv[row] = 1.0f / s;
}

__global__ __launch_bounds__(256)
void normalize_kernel(float* __restrict__ out, const float* __restrict__ inv)
{
    const int row = blockIdx.x;
    const float iv = __ldg(&inv[row]);
    float4* p = reinterpret_cast<float4*>(out + (size_t)row * S_);
    #pragma unroll
    for (int j = threadIdx.x; j < S_/4; j += 256) {
        float4 v = p[j];
        v.x *= iv; v.y *= iv; v.z *= iv; v.w *= iv;
        p[j] = v;
    }
}

// ---------------- launcher ----------------
extern "C" void kernel_launch(void* const* d_in, const int* in_sizes, int n_in,
                              void* d_out, int out_size)
{
    const float* x  = (const float*)d_in[0];
    const float* Wq = (const float*)d_in[1];
    const float* bq = (const float*)d_in[2];
    const float* Wk = (const float*)d_in[3];
    float* out = (float*)d_out;

    __nv_bfloat16 *xhi, *xlo, *m2hi, *m2lo, *uhi, *ulo;
    float *v2p, *rkp, *pptr, *invp;
    cudaGetSymbolAddress((void**)&xhi,  g_xhi);
    cudaGetSymbolAddress((void**)&xlo,  g_xlo);
    cudaGetSymbolAddress((void**)&m2hi, g_m2hi);
    cudaGetSymbolAddress((void**)&m2lo, g_m2lo);
    cudaGetSymbolAddress((void**)&uhi,  g_uhi);
    cudaGetSymbolAddress((void**)&ulo,  g_ulo);
    cudaGetSymbolAddress((void**)&v2p,  g_v2);
    cudaGetSymbolAddress((void**)&rkp,  g_rk);
    cudaGetSymbolAddress((void**)&pptr, g_psum);
    cudaGetSymbolAddress((void**)&invp, g_inv);

    cudaFuncSetAttribute(gemm_nt_kernel<0>, cudaFuncAttributeMaxDynamicSharedMemorySize, SMEM_DYN);
    cudaFuncSetAttribute(gemm_nt_kernel<1>, cudaFuncAttributeMaxDynamicSharedMemorySize, SMEM_DYN);

    // 1) preps: v2 = Wk@bq; split x (+rk); m2t = Wk@Wq^T (split)
    v2_kernel<<<D_/8, 256>>>(Wk, bq, v2p);
    split_x_rk_kernel<<<B_*S_/2, 256>>>(x, v2p, xhi, xlo, rkp);
    dim3 mg(D_/32, D_/32);
    m2t_kernel<<<mg, 256>>>(Wk, Wq, m2hi, m2lo);

    // 2) u = x @ M2 (stored bf16 hi/lo)
    dim3 pg(D_/BN, (B_*S_)/BM);          // (4, 128)
    gemm_nt_kernel<0><<<pg, 512, SMEM_DYN>>>(xhi, xlo, m2hi, m2lo, nullptr, uhi, ulo, nullptr, nullptr);

    // 3) scores: E = exp2(scale*(u x^T) + rk[n]) + row partial sums
    dim3 sg(S_/BN, S_/BM, B_);           // (16, 16, 8)
    gemm_nt_kernel<1><<<sg, 512, SMEM_DYN>>>(uhi, ulo, xhi, xlo, rkp, nullptr, nullptr, out, pptr);

    // 4) normalize
    invsum_kernel<<<B_*S_/256, 256>>>(pptr, invp);
    normalize_kernel<<<B_*S_, 256>>>(out, invp);
}